// round 16
// baseline (speedup 1.0000x reference)
#include <cuda_runtime.h>
#include <cuda_fp16.h>
#include <math.h>

#define N_NODES  50000
#define N_GRAPHS 500
#define N_EDGES  800000
#define D        128
#define HG_LD    (3 * D)   // 384

#define SCAN_BLK 256
#define N_SCAN_BLKS ((N_NODES + SCAN_BLK - 1) / SCAN_BLK)   // 196

// ---------------- scratch (no allocs) ----------------
__device__ __half g_xh[N_NODES * D];        // fp16 gather operand, pre-scaled by out_inv
__device__ __half g_aggh[N_NODES * D];      // fp16 aggregation (includes in_inv)
__device__ __half g_wh[3 * D * D];          // fp16 weights
__device__ float  g_out_inv[N_NODES];
__device__ float  g_in_inv[N_NODES];
__device__ int    g_deg_out[N_NODES];
__device__ int    g_deg_in[N_NODES];
__device__ int    g_off[N_NODES + 1];       // CSR offsets by dst
__device__ int    g_cursor[N_NODES];        // fill cursors
__device__ int    g_blk_sum[N_SCAN_BLKS];   // RAW per-block partial sums
__device__ int    g_edge_src[N_EDGES];      // src only (weight folded into g_xh)

// ---------------- 1: zero degs + hg ----------------
__global__ void zero_kernel(float* __restrict__ hg) {
    int i = blockIdx.x * blockDim.x + threadIdx.x;
    if (i < N_NODES) { g_deg_out[i] = 0; g_deg_in[i] = 0; }
    if (i < N_GRAPHS * HG_LD) hg[i] = 0.f;
}

// ---------------- 2: degree histogram + W -> fp16 (independent work, same launch) ----------------
__global__ void degree_kernel(const int* __restrict__ src, const int* __restrict__ dst,
                              const float* __restrict__ W0,
                              const float* __restrict__ W1,
                              const float* __restrict__ W2) {
    int i = blockIdx.x * blockDim.x + threadIdx.x;
    if (i < N_EDGES) {
        atomicAdd(&g_deg_out[src[i]], 1);
        atomicAdd(&g_deg_in[dst[i]], 1);
    }
    const int per = D * D / 4;   // 4096 uint2-groups per matrix
    if (i < 3 * per) {
        const float* W = (i < per) ? W0 : (i < 2 * per ? W1 : W2);
        int j = i % per;
        float4 v = reinterpret_cast<const float4*>(W)[j];
        __half2 h0 = __floats2half2_rn(v.x, v.y);
        __half2 h1 = __floats2half2_rn(v.z, v.w);
        uint2 pk;
        pk.x = *reinterpret_cast<unsigned int*>(&h0);
        pk.y = *reinterpret_cast<unsigned int*>(&h1);
        reinterpret_cast<uint2*>(g_wh)[i] = pk;
    }
}

// ---------------- 3: per-block partial sums of deg_in (raw, no scan) ----------------
__global__ void __launch_bounds__(SCAN_BLK)
scan_partial_kernel() {
    __shared__ int wsum[SCAN_BLK / 32];
    int i = blockIdx.x * SCAN_BLK + threadIdx.x;
    int v = (i < N_NODES) ? g_deg_in[i] : 0;
    #pragma unroll
    for (int o = 16; o > 0; o >>= 1) v += __shfl_down_sync(0xFFFFFFFF, v, o);
    int lane = threadIdx.x & 31, wid = threadIdx.x >> 5;
    if (lane == 0) wsum[wid] = v;
    __syncthreads();
    if (wid == 0) {
        int s = (lane < SCAN_BLK / 32) ? wsum[lane] : 0;
        #pragma unroll
        for (int o = 16; o > 0; o >>= 1) s += __shfl_down_sync(0xFFFFFFFF, s, o);
        if (lane == 0) g_blk_sum[blockIdx.x] = s;
    }
}

// ---------------- 4: addback (each block scans the raw partials itself) + inv norms ----------------
__global__ void __launch_bounds__(SCAN_BLK)
addback_inv_kernel() {
    __shared__ int rsum[SCAN_BLK / 32];
    __shared__ int wsum[SCAN_BLK / 32];
    __shared__ int s_base, s_all;

    int b    = blockIdx.x;
    int t    = threadIdx.x;
    int lane = t & 31, wid = t >> 5;

    // ---- block-reduce raw partials: base = sum(partials[0..b)), all = sum(all) ----
    int p    = (t < N_SCAN_BLKS) ? g_blk_sum[t] : 0;
    int plt  = (t < b) ? p : 0;
    // reduce plt
    #pragma unroll
    for (int o = 16; o > 0; o >>= 1) plt += __shfl_down_sync(0xFFFFFFFF, plt, o);
    if (lane == 0) rsum[wid] = plt;
    __syncthreads();
    if (wid == 0) {
        int s = (lane < SCAN_BLK / 32) ? rsum[lane] : 0;
        #pragma unroll
        for (int o = 16; o > 0; o >>= 1) s += __shfl_down_sync(0xFFFFFFFF, s, o);
        if (lane == 0) s_base = s;
    }
    __syncthreads();
    // reduce all partials (for total; cheap, done by every block, used by last)
    int pa = p;
    #pragma unroll
    for (int o = 16; o > 0; o >>= 1) pa += __shfl_down_sync(0xFFFFFFFF, pa, o);
    if (lane == 0) rsum[wid] = pa;
    __syncthreads();
    if (wid == 0) {
        int s = (lane < SCAN_BLK / 32) ? rsum[lane] : 0;
        #pragma unroll
        for (int o = 16; o > 0; o >>= 1) s += __shfl_down_sync(0xFFFFFFFF, s, o);
        if (lane == 0) s_all = s;
    }
    __syncthreads();

    // ---- intra-block inclusive scan of deg_in ----
    int i = b * SCAN_BLK + t;
    int v = (i < N_NODES) ? g_deg_in[i] : 0;
    int incl = v;
    #pragma unroll
    for (int o = 1; o < 32; o <<= 1) {
        int u = __shfl_up_sync(0xFFFFFFFF, incl, o);
        if (lane >= o) incl += u;
    }
    if (lane == 31) wsum[wid] = incl;
    __syncthreads();
    if (wid == 0 && lane < SCAN_BLK / 32) {
        int tt = wsum[lane];
        int ss = tt;
        #pragma unroll
        for (int o = 1; o < SCAN_BLK / 32; o <<= 1) {
            int u = __shfl_up_sync(0xFF, ss, o);
            if (lane >= o) ss += u;
        }
        wsum[lane] = ss - tt;
    }
    __syncthreads();
    int excl = incl - v + wsum[wid];

    if (i < N_NODES) {
        int off = s_base + excl;
        g_off[i]    = off;
        g_cursor[i] = off;
        g_out_inv[i] = rsqrtf(fmaxf((float)g_deg_out[i], 1.0f));
        g_in_inv[i]  = rsqrtf(fmaxf((float)v, 1.0f));
    }
    if (b == N_SCAN_BLKS - 1 && t == 0) g_off[N_NODES] = s_all;
}

// ---------------- 5: prep = bucket fill + feat*out_inv -> fp16 Xh ----------------
// N_NODES*D/4 = 1,600,000 = 2 * N_EDGES, so each of the 800K threads converts 2 items.
__global__ void prep_kernel(const int* __restrict__ src, const int* __restrict__ dst,
                            const float* __restrict__ feat) {
    int e = blockIdx.x * blockDim.x + threadIdx.x;
    if (e < N_EDGES) {
        int d = dst[e];
        int pos = atomicAdd(&g_cursor[d], 1);
        g_edge_src[pos] = src[e];
    }
    #pragma unroll
    for (int t = 0; t < 2; t++) {
        int i = e + t * N_EDGES;
        if (i < N_NODES * D / 4) {
            int row = i >> 5;   // D/4 = 32 items per row
            float w = g_out_inv[row];
            float4 v = reinterpret_cast<const float4*>(feat)[i];
            __half2 h0 = __floats2half2_rn(v.x * w, v.y * w);
            __half2 h1 = __floats2half2_rn(v.z * w, v.w * w);
            uint2 pk;
            pk.x = *reinterpret_cast<unsigned int*>(&h0);
            pk.y = *reinterpret_cast<unsigned int*>(&h1);
            reinterpret_cast<uint2*>(g_xh)[i] = pk;
        }
    }
}

// ---------------- gather: LDG.128 dual-edge, fp16 in / fp16 out ----------------
#define ACC8(v) { \
    float2 a0 = __half22float2(*reinterpret_cast<const __half2*>(&(v).x)); \
    float2 a1 = __half22float2(*reinterpret_cast<const __half2*>(&(v).y)); \
    float2 a2 = __half22float2(*reinterpret_cast<const __half2*>(&(v).z)); \
    float2 a3 = __half22float2(*reinterpret_cast<const __half2*>(&(v).w)); \
    acc[0] += a0.x; acc[1] += a0.y; acc[2] += a1.x; acc[3] += a1.y; \
    acc[4] += a2.x; acc[5] += a2.y; acc[6] += a3.x; acc[7] += a3.y; }

__global__ void __launch_bounds__(256)
gather_kernel() {
    int gtid = blockIdx.x * blockDim.x + threadIdx.x;
    int node = gtid >> 5;
    int lane = gtid & 31;
    if (node >= N_NODES) return;
    int half = lane >> 4;   // 0 or 1
    int sub  = lane & 15;   // column group: halves sub*8 .. sub*8+7

    int beg = g_off[node];
    int end = g_off[node + 1];

    const uint4* X4 = reinterpret_cast<const uint4*>(g_xh);   // 16 uint4 per row
    float acc[8];
    #pragma unroll
    for (int i = 0; i < 8; i++) acc[i] = 0.f;

    int j = beg;
    for (; j + 4 <= end; j += 4) {
        int s0 = g_edge_src[j + half];
        int s1 = g_edge_src[j + 2 + half];
        uint4 v0 = X4[s0 * 16 + sub];
        uint4 v1 = X4[s1 * 16 + sub];
        ACC8(v0)
        ACC8(v1)
    }
    if (j + 2 <= end) {
        int s0 = g_edge_src[j + half];
        uint4 v0 = X4[s0 * 16 + sub];
        ACC8(v0)
        j += 2;
    }
    if (j < end && half == 0) {
        int s0 = g_edge_src[j];
        uint4 v0 = X4[s0 * 16 + sub];
        ACC8(v0)
    }

    #pragma unroll
    for (int i = 0; i < 8; i++)
        acc[i] += __shfl_xor_sync(0xFFFFFFFF, acc[i], 16);

    if (half == 0) {
        float s = g_in_inv[node];
        __half2 p0 = __floats2half2_rn(acc[0] * s, acc[1] * s);
        __half2 p1 = __floats2half2_rn(acc[2] * s, acc[3] * s);
        __half2 p2 = __floats2half2_rn(acc[4] * s, acc[5] * s);
        __half2 p3 = __floats2half2_rn(acc[6] * s, acc[7] * s);
        uint4 pk;
        pk.x = *reinterpret_cast<unsigned int*>(&p0);
        pk.y = *reinterpret_cast<unsigned int*>(&p1);
        pk.z = *reinterpret_cast<unsigned int*>(&p2);
        pk.w = *reinterpret_cast<unsigned int*>(&p3);
        reinterpret_cast<uint4*>(g_aggh)[node * 16 + sub] = pk;
    }
}
#undef ACC8

// ---------------- HMMA GEMM + PReLU + pool ----------------
// C[64x128] = aggh_tile[64x128] @ Wh[128x128]; 8 warps, each 16x64 (8 x m16n8k16 per k-step).
#define TM 64
#define AS 136   // smem half-stride (136*2B = 272B)
#define CS 132   // smem float-stride for C overlay

__device__ __forceinline__ unsigned smem_u32(const void* p) {
    return (unsigned)__cvta_generic_to_shared(p);
}

__global__ void __launch_bounds__(256)
gemm_hmma_kernel(const __half* __restrict__ Wh,
                 const float* __restrict__ a_ptr,
                 const int* __restrict__ graph_id,
                 float* __restrict__ Hout_f32,
                 float* __restrict__ hg,
                 int hg_col_off,
                 int last_layer) {
    extern __shared__ char smraw[];
    __half* sA = reinterpret_cast<__half*>(smraw);             // 64 x AS
    __half* sW = reinterpret_cast<__half*>(smraw) + TM * AS;   // 128 x AS
    float*  sC = reinterpret_cast<float*>(smraw);              // 64 x CS (overlay, after sync)

    int tid  = threadIdx.x;
    int lane = tid & 31;
    int w    = tid >> 5;
    int row0 = blockIdx.x * TM;

    // stage W: 16384 halves = 2048 uint4
    {
        const uint4* Wv = reinterpret_cast<const uint4*>(Wh);
        for (int i = tid; i < 2048; i += 256) {
            int r = i >> 4, c8 = i & 15;
            *reinterpret_cast<uint4*>(&sW[r * AS + c8 * 8]) = Wv[i];
        }
    }
    // stage A: 1024 uint4
    {
        const uint4* Av = reinterpret_cast<const uint4*>(g_aggh);
        for (int i = tid; i < 1024; i += 256) {
            int r = i >> 4, c8 = i & 15;
            uint4 v = make_uint4(0u, 0u, 0u, 0u);
            if (row0 + r < N_NODES) v = Av[(row0 + r) * 16 + c8];
            *reinterpret_cast<uint4*>(&sA[r * AS + c8 * 8]) = v;
        }
    }
    __syncthreads();

    int m0 = (w >> 1) * 16;
    int n0 = (w & 1) * 64;

    float acc[8][4];
    #pragma unroll
    for (int nt = 0; nt < 8; nt++)
        #pragma unroll
        for (int q = 0; q < 4; q++) acc[nt][q] = 0.f;

    unsigned smA = smem_u32(sA);
    unsigned smW = smem_u32(sW);

    #pragma unroll
    for (int ks = 0; ks < 8; ks++) {
        unsigned a0, a1, a2, a3;
        unsigned aaddr = smA + ((m0 + (lane & 15)) * AS + ks * 16 + (lane >> 4) * 8) * 2;
        asm volatile("ldmatrix.sync.aligned.m8n8.x4.shared.b16 {%0,%1,%2,%3}, [%4];"
                     : "=r"(a0), "=r"(a1), "=r"(a2), "=r"(a3) : "r"(aaddr));
        #pragma unroll
        for (int nt = 0; nt < 8; nt++) {
            unsigned b0, b1;
            unsigned baddr = smW + ((ks * 16 + (lane & 15)) * AS + n0 + nt * 8) * 2;
            asm volatile("ldmatrix.sync.aligned.m8n8.x2.trans.shared.b16 {%0,%1}, [%2];"
                         : "=r"(b0), "=r"(b1) : "r"(baddr));
            asm volatile("mma.sync.aligned.m16n8k16.row.col.f32.f16.f16.f32 "
                         "{%0,%1,%2,%3}, {%4,%5,%6,%7}, {%8,%9}, {%0,%1,%2,%3};"
                         : "+f"(acc[nt][0]), "+f"(acc[nt][1]), "+f"(acc[nt][2]), "+f"(acc[nt][3])
                         : "r"(a0), "r"(a1), "r"(a2), "r"(a3), "r"(b0), "r"(b1));
        }
    }
    __syncthreads();   // done reading sA/sW; reuse as sC

    // scatter acc fragments into sC
    {
        int r0 = m0 + (lane >> 2);
        int c0 = n0 + (lane & 3) * 2;
        #pragma unroll
        for (int nt = 0; nt < 8; nt++) {
            int c = c0 + nt * 8;
            sC[r0 * CS + c]           = acc[nt][0];
            sC[r0 * CS + c + 1]       = acc[nt][1];
            sC[(r0 + 8) * CS + c]     = acc[nt][2];
            sC[(r0 + 8) * CS + c + 1] = acc[nt][3];
        }
    }
    __syncthreads();

    // epilogue: PReLU + store + pool (thread = 4 rows x 8 cols)
    int rg = tid >> 4;
    int cg = tid & 15;
    float alpha = __ldg(a_ptr);
    int colbase = cg * 8;

    int   grow[4];
    bool  valid[4];
    #pragma unroll
    for (int i = 0; i < 4; i++) {
        int row = row0 + rg * 4 + i;
        valid[i] = (row < N_NODES);
        grow[i]  = valid[i] ? __ldg(&graph_id[row]) : -1;
    }

    float hv[4][8];
    #pragma unroll
    for (int i = 0; i < 4; i++) {
        #pragma unroll
        for (int j = 0; j < 8; j++) {
            float z = sC[(rg * 4 + i) * CS + colbase + j];
            hv[i][j] = z > 0.f ? z : alpha * z;
        }
        if (valid[i]) {
            int row = row0 + rg * 4 + i;
            if (last_layer) {
                float4 s0 = make_float4(hv[i][0], hv[i][1], hv[i][2], hv[i][3]);
                float4 s1 = make_float4(hv[i][4], hv[i][5], hv[i][6], hv[i][7]);
                *reinterpret_cast<float4*>(&Hout_f32[row * D + colbase])     = s0;
                *reinterpret_cast<float4*>(&Hout_f32[row * D + colbase + 4]) = s1;
            } else {
                float wsc = g_out_inv[row];
                __half2 p0 = __floats2half2_rn(hv[i][0] * wsc, hv[i][1] * wsc);
                __half2 p1 = __floats2half2_rn(hv[i][2] * wsc, hv[i][3] * wsc);
                __half2 p2 = __floats2half2_rn(hv[i][4] * wsc, hv[i][5] * wsc);
                __half2 p3 = __floats2half2_rn(hv[i][6] * wsc, hv[i][7] * wsc);
                uint4 pk;
                pk.x = *reinterpret_cast<unsigned int*>(&p0);
                pk.y = *reinterpret_cast<unsigned int*>(&p1);
                pk.z = *reinterpret_cast<unsigned int*>(&p2);
                pk.w = *reinterpret_cast<unsigned int*>(&p3);
                *reinterpret_cast<uint4*>(&g_xh[row * D + colbase]) = pk;
            }
        }
    }

    bool same = valid[0] & valid[3] & (grow[0] == grow[1]) & (grow[1] == grow[2]) & (grow[2] == grow[3]);
    if (same) {
        float* base = &hg[grow[0] * HG_LD + hg_col_off + colbase];
        #pragma unroll
        for (int j = 0; j < 8; j++) {
            float s = hv[0][j] + hv[1][j] + hv[2][j] + hv[3][j];
            atomicAdd(base + j, s);
        }
    } else {
        #pragma unroll
        for (int i = 0; i < 4; i++) {
            if (!valid[i]) continue;
            float* base = &hg[grow[i] * HG_LD + hg_col_off + colbase];
            #pragma unroll
            for (int j = 0; j < 8; j++) atomicAdd(base + j, hv[i][j]);
        }
    }
}

// ---------------- launch ----------------
extern "C" void kernel_launch(void* const* d_in, const int* in_sizes, int n_in,
                              void* d_out, int out_size) {
    const float* feat = (const float*)d_in[0];
    const float* W0   = (const float*)d_in[1];
    const float* W1   = (const float*)d_in[2];
    const float* W2   = (const float*)d_in[3];
    const float* a0   = (const float*)d_in[4];
    const float* a1   = (const float*)d_in[5];
    const float* a2   = (const float*)d_in[6];
    const int*   src  = (const int*)d_in[7];
    const int*   dst  = (const int*)d_in[8];
    const int*   gid  = (const int*)d_in[9];

    float* out_h  = (float*)d_out;                 // [N_NODES, D]
    float* out_hg = (float*)d_out + N_NODES * D;   // [N_GRAPHS, 3*D]

    const int smem_bytes = (TM + D) * AS * sizeof(__half);   // 52224
    static bool attr_set = false;
    if (!attr_set) {
        cudaFuncSetAttribute(gemm_hmma_kernel,
                             cudaFuncAttributeMaxDynamicSharedMemorySize, smem_bytes);
        attr_set = true;
    }

    void* wh_sym = nullptr;
    cudaGetSymbolAddress(&wh_sym, g_wh);
    const __half* wh = (const __half*)wh_sym;

    // ---- build: 5 launches ----
    {
        int nz = N_GRAPHS * HG_LD;   // 192000, covers hg + node arrays
        zero_kernel<<<(nz + 255) / 256, 256>>>(out_hg);                          // #1
    }
    degree_kernel<<<(N_EDGES + 255) / 256, 256>>>(src, dst, W0, W1, W2);         // #2
    scan_partial_kernel<<<N_SCAN_BLKS, SCAN_BLK>>>();                            // #3
    addback_inv_kernel<<<N_SCAN_BLKS, SCAN_BLK>>>();                             // #4
    prep_kernel<<<(N_EDGES + 255) / 256, 256>>>(src, dst, feat);                 // #5

    const float* as[3] = {a0, a1, a2};

    int gather_blocks = (N_NODES * 32 + 255) / 256;
    int gemm_blocks   = (N_NODES + TM - 1) / TM;

    for (int l = 0; l < 3; l++) {
        gather_kernel<<<gather_blocks, 256>>>();                                 // #6,8,10
        gemm_hmma_kernel<<<gemm_blocks, 256, smem_bytes>>>(                      // #7,9,11
            wh + l * D * D, as[l], gid, out_h, out_hg, l * D, (l == 2) ? 1 : 0);
    }
}

// round 17
// speedup vs baseline: 1.0423x; 1.0423x over previous
#include <cuda_runtime.h>
#include <cuda_fp16.h>
#include <math.h>

#define N_NODES  50000
#define N_GRAPHS 500
#define N_EDGES  800000
#define D        128
#define HG_LD    (3 * D)   // 384

#define SCAN_BLK 256
#define N_SCAN_BLKS ((N_NODES + SCAN_BLK - 1) / SCAN_BLK)   // 196

// ---------------- scratch (no allocs) ----------------
__device__ __half g_xh[N_NODES * D];        // fp16 gather operand, pre-scaled by out_inv
__device__ __half g_aggh[N_NODES * D];      // fp16 aggregation (includes in_inv)
__device__ __half g_wh[3 * D * D];          // fp16 weights
__device__ float  g_out_inv[N_NODES];
__device__ float  g_in_inv[N_NODES];
__device__ int    g_deg_out[N_NODES];
__device__ int    g_deg_in[N_NODES];
__device__ int    g_off[N_NODES + 1];       // CSR offsets by dst
__device__ int    g_cursor[N_NODES];        // fill cursors
__device__ int    g_blk_sum[N_SCAN_BLKS];   // RAW per-block partial sums
__device__ int    g_edge_src[N_EDGES];      // src only (weight folded into g_xh)

// ---------------- 1: zero degs + hg ----------------
__global__ void zero_kernel(float* __restrict__ hg) {
    int i = blockIdx.x * blockDim.x + threadIdx.x;
    if (i < N_NODES) { g_deg_out[i] = 0; g_deg_in[i] = 0; }
    if (i < N_GRAPHS * HG_LD) hg[i] = 0.f;
}

// ---------------- 2: degree histogram + W -> fp16 (independent work, same launch) ----------------
__global__ void degree_kernel(const int* __restrict__ src, const int* __restrict__ dst,
                              const float* __restrict__ W0,
                              const float* __restrict__ W1,
                              const float* __restrict__ W2) {
    int i = blockIdx.x * blockDim.x + threadIdx.x;
    if (i < N_EDGES) {
        atomicAdd(&g_deg_out[src[i]], 1);
        atomicAdd(&g_deg_in[dst[i]], 1);
    }
    const int per = D * D / 4;   // 4096 uint2-groups per matrix
    if (i < 3 * per) {
        const float* W = (i < per) ? W0 : (i < 2 * per ? W1 : W2);
        int j = i % per;
        float4 v = reinterpret_cast<const float4*>(W)[j];
        __half2 h0 = __floats2half2_rn(v.x, v.y);
        __half2 h1 = __floats2half2_rn(v.z, v.w);
        uint2 pk;
        pk.x = *reinterpret_cast<unsigned int*>(&h0);
        pk.y = *reinterpret_cast<unsigned int*>(&h1);
        reinterpret_cast<uint2*>(g_wh)[i] = pk;
    }
}

// ---------------- 3: per-block partial sums of deg_in (raw, no scan) ----------------
__global__ void __launch_bounds__(SCAN_BLK)
scan_partial_kernel() {
    __shared__ int wsum[SCAN_BLK / 32];
    int i = blockIdx.x * SCAN_BLK + threadIdx.x;
    int v = (i < N_NODES) ? g_deg_in[i] : 0;
    #pragma unroll
    for (int o = 16; o > 0; o >>= 1) v += __shfl_down_sync(0xFFFFFFFF, v, o);
    int lane = threadIdx.x & 31, wid = threadIdx.x >> 5;
    if (lane == 0) wsum[wid] = v;
    __syncthreads();
    if (wid == 0) {
        int s = (lane < SCAN_BLK / 32) ? wsum[lane] : 0;
        #pragma unroll
        for (int o = 16; o > 0; o >>= 1) s += __shfl_down_sync(0xFFFFFFFF, s, o);
        if (lane == 0) g_blk_sum[blockIdx.x] = s;
    }
}

// ---------------- 4: addback (each block scans the raw partials itself) + inv norms ----------------
__global__ void __launch_bounds__(SCAN_BLK)
addback_inv_kernel() {
    __shared__ int rsum[SCAN_BLK / 32];
    __shared__ int wsum[SCAN_BLK / 32];
    __shared__ int s_base, s_all;

    int b    = blockIdx.x;
    int t    = threadIdx.x;
    int lane = t & 31, wid = t >> 5;

    // ---- block-reduce raw partials: base = sum(partials[0..b)), all = sum(all) ----
    int p    = (t < N_SCAN_BLKS) ? g_blk_sum[t] : 0;
    int plt  = (t < b) ? p : 0;
    #pragma unroll
    for (int o = 16; o > 0; o >>= 1) plt += __shfl_down_sync(0xFFFFFFFF, plt, o);
    if (lane == 0) rsum[wid] = plt;
    __syncthreads();
    if (wid == 0) {
        int s = (lane < SCAN_BLK / 32) ? rsum[lane] : 0;
        #pragma unroll
        for (int o = 16; o > 0; o >>= 1) s += __shfl_down_sync(0xFFFFFFFF, s, o);
        if (lane == 0) s_base = s;
    }
    __syncthreads();
    int pa = p;
    #pragma unroll
    for (int o = 16; o > 0; o >>= 1) pa += __shfl_down_sync(0xFFFFFFFF, pa, o);
    if (lane == 0) rsum[wid] = pa;
    __syncthreads();
    if (wid == 0) {
        int s = (lane < SCAN_BLK / 32) ? rsum[lane] : 0;
        #pragma unroll
        for (int o = 16; o > 0; o >>= 1) s += __shfl_down_sync(0xFFFFFFFF, s, o);
        if (lane == 0) s_all = s;
    }
    __syncthreads();

    // ---- intra-block inclusive scan of deg_in ----
    int i = b * SCAN_BLK + t;
    int v = (i < N_NODES) ? g_deg_in[i] : 0;
    int incl = v;
    #pragma unroll
    for (int o = 1; o < 32; o <<= 1) {
        int u = __shfl_up_sync(0xFFFFFFFF, incl, o);
        if (lane >= o) incl += u;
    }
    if (lane == 31) wsum[wid] = incl;
    __syncthreads();
    if (wid == 0 && lane < SCAN_BLK / 32) {
        int tt = wsum[lane];
        int ss = tt;
        #pragma unroll
        for (int o = 1; o < SCAN_BLK / 32; o <<= 1) {
            int u = __shfl_up_sync(0xFF, ss, o);
            if (lane >= o) ss += u;
        }
        wsum[lane] = ss - tt;
    }
    __syncthreads();
    int excl = incl - v + wsum[wid];

    if (i < N_NODES) {
        int off = s_base + excl;
        g_off[i]    = off;
        g_cursor[i] = off;
        g_out_inv[i] = rsqrtf(fmaxf((float)g_deg_out[i], 1.0f));
        g_in_inv[i]  = rsqrtf(fmaxf((float)v, 1.0f));
    }
    if (b == N_SCAN_BLKS - 1 && t == 0) g_off[N_NODES] = s_all;
}

// ---------------- 5: prep = bucket fill + feat*out_inv -> fp16 Xh ----------------
__global__ void prep_kernel(const int* __restrict__ src, const int* __restrict__ dst,
                            const float* __restrict__ feat) {
    int e = blockIdx.x * blockDim.x + threadIdx.x;
    if (e < N_EDGES) {
        int d = dst[e];
        int pos = atomicAdd(&g_cursor[d], 1);
        g_edge_src[pos] = src[e];
    }
    #pragma unroll
    for (int t = 0; t < 2; t++) {
        int i = e + t * N_EDGES;
        if (i < N_NODES * D / 4) {
            int row = i >> 5;   // D/4 = 32 items per row
            float w = g_out_inv[row];
            float4 v = reinterpret_cast<const float4*>(feat)[i];
            __half2 h0 = __floats2half2_rn(v.x * w, v.y * w);
            __half2 h1 = __floats2half2_rn(v.z * w, v.w * w);
            uint2 pk;
            pk.x = *reinterpret_cast<unsigned int*>(&h0);
            pk.y = *reinterpret_cast<unsigned int*>(&h1);
            reinterpret_cast<uint2*>(g_xh)[i] = pk;
        }
    }
}

// ---------------- gather: LDG.128 dual-edge, fp16 in / fp16 out (unchanged, proven) ----------------
#define ACC8(v) { \
    float2 a0 = __half22float2(*reinterpret_cast<const __half2*>(&(v).x)); \
    float2 a1 = __half22float2(*reinterpret_cast<const __half2*>(&(v).y)); \
    float2 a2 = __half22float2(*reinterpret_cast<const __half2*>(&(v).z)); \
    float2 a3 = __half22float2(*reinterpret_cast<const __half2*>(&(v).w)); \
    acc[0] += a0.x; acc[1] += a0.y; acc[2] += a1.x; acc[3] += a1.y; \
    acc[4] += a2.x; acc[5] += a2.y; acc[6] += a3.x; acc[7] += a3.y; }

__global__ void __launch_bounds__(256)
gather_kernel() {
    int gtid = blockIdx.x * blockDim.x + threadIdx.x;
    int node = gtid >> 5;
    int lane = gtid & 31;
    if (node >= N_NODES) return;
    int half = lane >> 4;
    int sub  = lane & 15;

    int beg = g_off[node];
    int end = g_off[node + 1];

    const uint4* X4 = reinterpret_cast<const uint4*>(g_xh);
    float acc[8];
    #pragma unroll
    for (int i = 0; i < 8; i++) acc[i] = 0.f;

    int j = beg;
    for (; j + 4 <= end; j += 4) {
        int s0 = g_edge_src[j + half];
        int s1 = g_edge_src[j + 2 + half];
        uint4 v0 = X4[s0 * 16 + sub];
        uint4 v1 = X4[s1 * 16 + sub];
        ACC8(v0)
        ACC8(v1)
    }
    if (j + 2 <= end) {
        int s0 = g_edge_src[j + half];
        uint4 v0 = X4[s0 * 16 + sub];
        ACC8(v0)
        j += 2;
    }
    if (j < end && half == 0) {
        int s0 = g_edge_src[j];
        uint4 v0 = X4[s0 * 16 + sub];
        ACC8(v0)
    }

    #pragma unroll
    for (int i = 0; i < 8; i++)
        acc[i] += __shfl_xor_sync(0xFFFFFFFF, acc[i], 16);

    if (half == 0) {
        float s = g_in_inv[node];
        __half2 p0 = __floats2half2_rn(acc[0] * s, acc[1] * s);
        __half2 p1 = __floats2half2_rn(acc[2] * s, acc[3] * s);
        __half2 p2 = __floats2half2_rn(acc[4] * s, acc[5] * s);
        __half2 p3 = __floats2half2_rn(acc[6] * s, acc[7] * s);
        uint4 pk;
        pk.x = *reinterpret_cast<unsigned int*>(&p0);
        pk.y = *reinterpret_cast<unsigned int*>(&p1);
        pk.z = *reinterpret_cast<unsigned int*>(&p2);
        pk.w = *reinterpret_cast<unsigned int*>(&p3);
        reinterpret_cast<uint4*>(g_aggh)[node * 16 + sub] = pk;
    }
}
#undef ACC8

// ---------------- HMMA GEMM + PReLU + pool, TM=128 ----------------
// C[128x128] = aggh_tile[128x128] @ Wh[128x128]; 8 warps, each a 16x128 strip
// (16 x m16n8k16 per k-step). Halves per-layer W staging traffic vs TM=64.
#define TM 128
#define AS 136   // smem half-stride (136*2B = 272B)
#define CS 132   // smem float-stride for C overlay

__device__ __forceinline__ unsigned smem_u32(const void* p) {
    return (unsigned)__cvta_generic_to_shared(p);
}

__global__ void __launch_bounds__(256)
gemm_hmma_kernel(const __half* __restrict__ Wh,
                 const float* __restrict__ a_ptr,
                 const int* __restrict__ graph_id,
                 float* __restrict__ Hout_f32,
                 float* __restrict__ hg,
                 int hg_col_off,
                 int last_layer) {
    extern __shared__ char smraw[];
    __half* sA = reinterpret_cast<__half*>(smraw);             // 128 x AS halves
    __half* sW = reinterpret_cast<__half*>(smraw) + TM * AS;   // 128 x AS halves
    float*  sC = reinterpret_cast<float*>(smraw);              // 128 x CS floats (overlay)

    int tid  = threadIdx.x;
    int lane = tid & 31;
    int w    = tid >> 5;
    int row0 = blockIdx.x * TM;

    // stage W: 16384 halves = 2048 uint4
    {
        const uint4* Wv = reinterpret_cast<const uint4*>(Wh);
        for (int i = tid; i < 2048; i += 256) {
            int r = i >> 4, c8 = i & 15;
            *reinterpret_cast<uint4*>(&sW[r * AS + c8 * 8]) = Wv[i];
        }
    }
    // stage A: 128 rows x 16 uint4 = 2048 uint4
    {
        const uint4* Av = reinterpret_cast<const uint4*>(g_aggh);
        for (int i = tid; i < 2048; i += 256) {
            int r = i >> 4, c8 = i & 15;
            uint4 v = make_uint4(0u, 0u, 0u, 0u);
            if (row0 + r < N_NODES) v = Av[(row0 + r) * 16 + c8];
            *reinterpret_cast<uint4*>(&sA[r * AS + c8 * 8]) = v;
        }
    }
    __syncthreads();

    int m0 = w * 16;   // warp strip: rows m0..m0+15, all 128 cols

    float acc[16][4];
    #pragma unroll
    for (int nt = 0; nt < 16; nt++)
        #pragma unroll
        for (int q = 0; q < 4; q++) acc[nt][q] = 0.f;

    unsigned smA = smem_u32(sA);
    unsigned smW = smem_u32(sW);

    #pragma unroll
    for (int ks = 0; ks < 8; ks++) {
        unsigned a0, a1, a2, a3;
        unsigned aaddr = smA + ((m0 + (lane & 15)) * AS + ks * 16 + (lane >> 4) * 8) * 2;
        asm volatile("ldmatrix.sync.aligned.m8n8.x4.shared.b16 {%0,%1,%2,%3}, [%4];"
                     : "=r"(a0), "=r"(a1), "=r"(a2), "=r"(a3) : "r"(aaddr));
        #pragma unroll
        for (int nt = 0; nt < 16; nt++) {
            unsigned b0, b1;
            unsigned baddr = smW + ((ks * 16 + (lane & 15)) * AS + nt * 8) * 2;
            asm volatile("ldmatrix.sync.aligned.m8n8.x2.trans.shared.b16 {%0,%1}, [%2];"
                         : "=r"(b0), "=r"(b1) : "r"(baddr));
            asm volatile("mma.sync.aligned.m16n8k16.row.col.f32.f16.f16.f32 "
                         "{%0,%1,%2,%3}, {%4,%5,%6,%7}, {%8,%9}, {%0,%1,%2,%3};"
                         : "+f"(acc[nt][0]), "+f"(acc[nt][1]), "+f"(acc[nt][2]), "+f"(acc[nt][3])
                         : "r"(a0), "r"(a1), "r"(a2), "r"(a3), "r"(b0), "r"(b1));
        }
    }
    __syncthreads();   // done reading sA/sW; reuse as sC

    // scatter acc fragments into sC
    {
        int r0 = m0 + (lane >> 2);
        int c0 = (lane & 3) * 2;
        #pragma unroll
        for (int nt = 0; nt < 16; nt++) {
            int c = c0 + nt * 8;
            sC[r0 * CS + c]           = acc[nt][0];
            sC[r0 * CS + c + 1]       = acc[nt][1];
            sC[(r0 + 8) * CS + c]     = acc[nt][2];
            sC[(r0 + 8) * CS + c + 1] = acc[nt][3];
        }
    }
    __syncthreads();

    // epilogue: PReLU + store + pool (thread = 8 rows x 8 cols)
    int rg = tid >> 4;   // 0..15 -> rows rg*8 .. rg*8+7
    int cg = tid & 15;   // cols cg*8 .. cg*8+7
    float alpha = __ldg(a_ptr);
    int colbase = cg * 8;

    int   grow[8];
    bool  valid[8];
    #pragma unroll
    for (int i = 0; i < 8; i++) {
        int row = row0 + rg * 8 + i;
        valid[i] = (row < N_NODES);
        grow[i]  = valid[i] ? __ldg(&graph_id[row]) : -1;
    }

    float hv[8][8];
    #pragma unroll
    for (int i = 0; i < 8; i++) {
        #pragma unroll
        for (int j = 0; j < 8; j++) {
            float z = sC[(rg * 8 + i) * CS + colbase + j];
            hv[i][j] = z > 0.f ? z : alpha * z;
        }
        if (valid[i]) {
            int row = row0 + rg * 8 + i;
            if (last_layer) {
                float4 s0 = make_float4(hv[i][0], hv[i][1], hv[i][2], hv[i][3]);
                float4 s1 = make_float4(hv[i][4], hv[i][5], hv[i][6], hv[i][7]);
                *reinterpret_cast<float4*>(&Hout_f32[row * D + colbase])     = s0;
                *reinterpret_cast<float4*>(&Hout_f32[row * D + colbase + 4]) = s1;
            } else {
                float wsc = g_out_inv[row];
                __half2 p0 = __floats2half2_rn(hv[i][0] * wsc, hv[i][1] * wsc);
                __half2 p1 = __floats2half2_rn(hv[i][2] * wsc, hv[i][3] * wsc);
                __half2 p2 = __floats2half2_rn(hv[i][4] * wsc, hv[i][5] * wsc);
                __half2 p3 = __floats2half2_rn(hv[i][6] * wsc, hv[i][7] * wsc);
                uint4 pk;
                pk.x = *reinterpret_cast<unsigned int*>(&p0);
                pk.y = *reinterpret_cast<unsigned int*>(&p1);
                pk.z = *reinterpret_cast<unsigned int*>(&p2);
                pk.w = *reinterpret_cast<unsigned int*>(&p3);
                *reinterpret_cast<uint4*>(&g_xh[row * D + colbase]) = pk;
            }
        }
    }

    // graph pooling: collapse all 8 rows when same graph (graphs avg ~100 rows)
    bool same = valid[0] & valid[7];
    #pragma unroll
    for (int i = 1; i < 8; i++) same &= (grow[i] == grow[0]);
    if (same) {
        float* base = &hg[grow[0] * HG_LD + hg_col_off + colbase];
        #pragma unroll
        for (int j = 0; j < 8; j++) {
            float s = 0.f;
            #pragma unroll
            for (int i = 0; i < 8; i++) s += hv[i][j];
            atomicAdd(base + j, s);
        }
    } else {
        #pragma unroll
        for (int i = 0; i < 8; i++) {
            if (!valid[i]) continue;
            float* base = &hg[grow[i] * HG_LD + hg_col_off + colbase];
            #pragma unroll
            for (int j = 0; j < 8; j++) atomicAdd(base + j, hv[i][j]);
        }
    }
}

// ---------------- launch ----------------
extern "C" void kernel_launch(void* const* d_in, const int* in_sizes, int n_in,
                              void* d_out, int out_size) {
    const float* feat = (const float*)d_in[0];
    const float* W0   = (const float*)d_in[1];
    const float* W1   = (const float*)d_in[2];
    const float* W2   = (const float*)d_in[3];
    const float* a0   = (const float*)d_in[4];
    const float* a1   = (const float*)d_in[5];
    const float* a2   = (const float*)d_in[6];
    const int*   src  = (const int*)d_in[7];
    const int*   dst  = (const int*)d_in[8];
    const int*   gid  = (const int*)d_in[9];

    float* out_h  = (float*)d_out;                 // [N_NODES, D]
    float* out_hg = (float*)d_out + N_NODES * D;   // [N_GRAPHS, 3*D]

    const int smem_bytes = 2 * TM * AS * sizeof(__half);   // 69632
    static bool attr_set = false;
    if (!attr_set) {
        cudaFuncSetAttribute(gemm_hmma_kernel,
                             cudaFuncAttributeMaxDynamicSharedMemorySize, smem_bytes);
        attr_set = true;
    }

    void* wh_sym = nullptr;
    cudaGetSymbolAddress(&wh_sym, g_wh);
    const __half* wh = (const __half*)wh_sym;

    // ---- build: 5 launches ----
    {
        int nz = N_GRAPHS * HG_LD;   // 192000, covers hg + node arrays
        zero_kernel<<<(nz + 255) / 256, 256>>>(out_hg);                          // #1
    }
    degree_kernel<<<(N_EDGES + 255) / 256, 256>>>(src, dst, W0, W1, W2);         // #2
    scan_partial_kernel<<<N_SCAN_BLKS, SCAN_BLK>>>();                            // #3
    addback_inv_kernel<<<N_SCAN_BLKS, SCAN_BLK>>>();                             // #4
    prep_kernel<<<(N_EDGES + 255) / 256, 256>>>(src, dst, feat);                 // #5

    const float* as[3] = {a0, a1, a2};

    int gather_blocks = (N_NODES * 32 + 255) / 256;
    int gemm_blocks   = (N_NODES + TM - 1) / TM;   // 391

    for (int l = 0; l < 3; l++) {
        gather_kernel<<<gather_blocks, 256>>>();                                 // #6,8,10
        gemm_hmma_kernel<<<gemm_blocks, 256, smem_bytes>>>(                      // #7,9,11
            wh + l * D * D, as[l], gid, out_h, out_hg, l * D, (l == 2) ? 1 : 0);
    }
}